// round 2
// baseline (speedup 1.0000x reference)
#include <cuda_runtime.h>
#include <math.h>

#define HEADS   16
#define D_MODEL 1024
#define DK      64
#define BATCH   2
#define SEQ     2048
#define MROWS   (BATCH * SEQ)   // 4096

// ---------------- scratch (device globals; no allocation allowed) ----------
__device__ float g_q[MROWS * D_MODEL];     // [B*H, S, DK]
__device__ float g_k[MROWS * D_MODEL];     // [B*H, S, DK]
__device__ float g_v[MROWS * D_MODEL];     // [B*H, S, DK]
__device__ float g_ctx[MROWS * D_MODEL];   // [B, S, D_MODEL] (concat layout)

// ---------------------------------------------------------------------------
// SGEMM: C[M,N] = A[M,K] @ W[K,N] + bias, M=4096, N=K=1024.
// 128x128 block tile, BK=8, 256 threads, 8x8 per-thread micro-tile.
// SRC:  0 -> A comes from the A_in parameter, 1 -> A = g_ctx
// DEST: 0 -> C param row-major, 1/2/3 -> g_q/g_k/g_v in [B*H, S, DK] layout
// ---------------------------------------------------------------------------
template<int SRC, int DEST>
__global__ __launch_bounds__(256)
void sgemm_kernel(const float* __restrict__ A_in, const float* __restrict__ W,
                  const float* __restrict__ bias, float* __restrict__ C)
{
    constexpr int K = D_MODEL;
    constexpr int N = D_MODEL;
    const float* A = (SRC == 0) ? A_in : g_ctx;

    __shared__ float As[8][128];   // transposed: As[k][m]
    __shared__ float Bs[8][128];   // Bs[k][n]

    const int tid = threadIdx.x;
    const int ty  = tid >> 4;        // 0..15
    const int tx  = tid & 15;        // 0..15
    const int m0  = blockIdx.y * 128;
    const int n0  = blockIdx.x * 128;

    // global->smem load assignments
    const int aRow = tid >> 1;            // 0..127
    const int aCol = (tid & 1) << 2;      // 0 or 4
    const int bRow = tid >> 5;            // 0..7
    const int bCol = (tid & 31) << 2;     // 0..124

    const float* Ap = A + (size_t)(m0 + aRow) * K + aCol;
    const float* Wp = W + (size_t)bRow * N + n0 + bCol;

    float acc[8][8];
    #pragma unroll
    for (int i = 0; i < 8; i++)
        #pragma unroll
        for (int j = 0; j < 8; j++) acc[i][j] = 0.0f;

    for (int k0 = 0; k0 < K; k0 += 8) {
        const float4 av = *(const float4*)(Ap + k0);
        const float4 wv = *(const float4*)(Wp + (size_t)k0 * N);
        As[aCol + 0][aRow] = av.x;
        As[aCol + 1][aRow] = av.y;
        As[aCol + 2][aRow] = av.z;
        As[aCol + 3][aRow] = av.w;
        *(float4*)&Bs[bRow][bCol] = wv;
        __syncthreads();

        #pragma unroll
        for (int k = 0; k < 8; k++) {
            float ra[8], rb[8];
            *(float4*)&ra[0] = *(const float4*)&As[k][ty * 8];
            *(float4*)&ra[4] = *(const float4*)&As[k][ty * 8 + 4];
            *(float4*)&rb[0] = *(const float4*)&Bs[k][tx * 8];
            *(float4*)&rb[4] = *(const float4*)&Bs[k][tx * 8 + 4];
            #pragma unroll
            for (int i = 0; i < 8; i++)
                #pragma unroll
                for (int j = 0; j < 8; j++)
                    acc[i][j] = fmaf(ra[i], rb[j], acc[i][j]);
        }
        __syncthreads();
    }

    #pragma unroll
    for (int i = 0; i < 8; i++) {
        const int row = m0 + ty * 8 + i;
        #pragma unroll
        for (int j = 0; j < 8; j++) {
            const int col = n0 + tx * 8 + j;
            const float v = acc[i][j] + bias[col];
            if (DEST == 0) {
                C[(size_t)row * N + col] = v;
            } else {
                float* dst = (DEST == 1) ? g_q : (DEST == 2) ? g_k : g_v;
                const int b = row >> 11;            // row / SEQ
                const int s = row & (SEQ - 1);
                const int h = col >> 6;             // col / DK
                const int d = col & (DK - 1);
                dst[((size_t)(b * HEADS + h) * SEQ + s) * DK + d] = v;
            }
        }
    }
}

// ---------------------------------------------------------------------------
// Flash attention, fp32. One CTA = 64 query rows of one (b,h) pair.
// Online softmax over 32 key tiles of 64. P reuses the K smem buffer.
// ---------------------------------------------------------------------------
#define AP 65   // smem row pitch (pad to dodge bank conflicts)

__device__ __forceinline__ float redmax16(float v) {
    #pragma unroll
    for (int off = 8; off > 0; off >>= 1)
        v = fmaxf(v, __shfl_xor_sync(0xffffffffu, v, off, 16));
    return v;
}
__device__ __forceinline__ float redsum16(float v) {
    #pragma unroll
    for (int off = 8; off > 0; off >>= 1)
        v += __shfl_xor_sync(0xffffffffu, v, off, 16);
    return v;
}

__global__ __launch_bounds__(256)
void attn_kernel()
{
    extern __shared__ float sm[];
    float* Qs = sm;                 // [64][AP]
    float* Ks = Qs + 64 * AP;       // [64][AP], reused as P after scores
    float* Vs = Ks + 64 * AP;       // [64][AP]

    const int tid = threadIdx.x;
    const int ty  = tid >> 4;       // 0..15 -> query rows 4*ty..4*ty+3
    const int tx  = tid & 15;       // 0..15 -> key cols / d cols 4*tx..4*tx+3
    const int qt  = blockIdx.x;     // 0..31 query tile
    const int bh  = blockIdx.y;     // 0..31 (b*HEADS + h)

    const float* Qg = g_q + (size_t)bh * SEQ * DK + (size_t)qt * 64 * DK;
    const float* Kg = g_k + (size_t)bh * SEQ * DK;
    const float* Vg = g_v + (size_t)bh * SEQ * DK;

    // load Q tile, folding in 1/sqrt(dk) = 0.125
    for (int i = tid; i < 1024; i += 256) {
        const int r = i >> 4;
        const int c = (i & 15) << 2;
        const float4 qv = *(const float4*)(Qg + r * DK + c);
        Qs[r * AP + c + 0] = qv.x * 0.125f;
        Qs[r * AP + c + 1] = qv.y * 0.125f;
        Qs[r * AP + c + 2] = qv.z * 0.125f;
        Qs[r * AP + c + 3] = qv.w * 0.125f;
    }

    float o[4][4];
    float m_i[4], l_i[4];
    #pragma unroll
    for (int r = 0; r < 4; r++) {
        m_i[r] = -INFINITY;
        l_i[r] = 0.0f;
        #pragma unroll
        for (int c = 0; c < 4; c++) o[r][c] = 0.0f;
    }
    __syncthreads();

    for (int kt = 0; kt < SEQ / 64; kt++) {
        const float* Kt = Kg + (size_t)kt * 64 * DK;
        const float* Vt = Vg + (size_t)kt * 64 * DK;
        for (int i = tid; i < 1024; i += 256) {
            const int r = i >> 4;
            const int c = (i & 15) << 2;
            const float4 kv = *(const float4*)(Kt + r * DK + c);
            const float4 vv = *(const float4*)(Vt + r * DK + c);
            Ks[r * AP + c + 0] = kv.x; Ks[r * AP + c + 1] = kv.y;
            Ks[r * AP + c + 2] = kv.z; Ks[r * AP + c + 3] = kv.w;
            Vs[r * AP + c + 0] = vv.x; Vs[r * AP + c + 1] = vv.y;
            Vs[r * AP + c + 2] = vv.z; Vs[r * AP + c + 3] = vv.w;
        }
        __syncthreads();

        // scores: s[r][c] = (Q*scale) . K over d
        float s[4][4];
        #pragma unroll
        for (int r = 0; r < 4; r++)
            #pragma unroll
            for (int c = 0; c < 4; c++) s[r][c] = 0.0f;

        #pragma unroll 4
        for (int d = 0; d < 64; d++) {
            float qv[4], kv[4];
            #pragma unroll
            for (int r = 0; r < 4; r++) qv[r] = Qs[(ty * 4 + r) * AP + d];
            #pragma unroll
            for (int c = 0; c < 4; c++) kv[c] = Ks[(tx * 4 + c) * AP + d];
            #pragma unroll
            for (int r = 0; r < 4; r++)
                #pragma unroll
                for (int c = 0; c < 4; c++)
                    s[r][c] = fmaf(qv[r], kv[c], s[r][c]);
        }

        // online softmax update (per-row reductions across the 16 tx lanes)
        float p[4][4];
        #pragma unroll
        for (int r = 0; r < 4; r++) {
            float tm = fmaxf(fmaxf(s[r][0], s[r][1]), fmaxf(s[r][2], s[r][3]));
            tm = redmax16(tm);
            const float mn = fmaxf(m_i[r], tm);
            const float alpha = __expf(m_i[r] - mn);
            float rs = 0.0f;
            #pragma unroll
            for (int c = 0; c < 4; c++) {
                p[r][c] = __expf(s[r][c] - mn);
                rs += p[r][c];
            }
            rs = redsum16(rs);
            l_i[r] = l_i[r] * alpha + rs;
            m_i[r] = mn;
            #pragma unroll
            for (int c = 0; c < 4; c++) o[r][c] *= alpha;
        }

        __syncthreads();   // everyone done reading Ks -> safe to overwrite with P
        #pragma unroll
        for (int r = 0; r < 4; r++)
            #pragma unroll
            for (int c = 0; c < 4; c++)
                Ks[(ty * 4 + r) * AP + tx * 4 + c] = p[r][c];
        __syncthreads();

        // O += P @ V  (P in Ks buffer)
        #pragma unroll 4
        for (int j = 0; j < 64; j++) {
            float pv[4], vv[4];
            #pragma unroll
            for (int r = 0; r < 4; r++) pv[r] = Ks[(ty * 4 + r) * AP + j];
            #pragma unroll
            for (int c = 0; c < 4; c++) vv[c] = Vs[j * AP + tx * 4 + c];
            #pragma unroll
            for (int r = 0; r < 4; r++)
                #pragma unroll
                for (int c = 0; c < 4; c++)
                    o[r][c] = fmaf(pv[r], vv[c], o[r][c]);
        }
        __syncthreads();   // before next tile overwrites Ks/Vs
    }

    // normalize and write ctx in [B, S, D_MODEL] concat layout
    const int b = bh >> 4;
    const int h = bh & 15;
    #pragma unroll
    for (int r = 0; r < 4; r++) {
        const float inv = 1.0f / l_i[r];
        const int srow = qt * 64 + ty * 4 + r;
        #pragma unroll
        for (int c = 0; c < 4; c++) {
            g_ctx[((size_t)(b * SEQ + srow)) * D_MODEL + h * DK + tx * 4 + c] =
                o[r][c] * inv;
        }
    }
}

// ---------------------------------------------------------------------------
// Re-bench of R1 source (R1 bench was an infra failure; kernel never ran).
// ---------------------------------------------------------------------------
extern "C" void kernel_launch(void* const* d_in, const int* in_sizes, int n_in,
                              void* d_out, int out_size)
{
    const float* query = (const float*)d_in[0];
    const float* key_  = (const float*)d_in[1];
    const float* value = (const float*)d_in[2];
    const float* Wq = (const float*)d_in[3];
    const float* bq = (const float*)d_in[4];
    const float* Wk = (const float*)d_in[5];
    const float* bk = (const float*)d_in[6];
    const float* Wv = (const float*)d_in[7];
    const float* bv = (const float*)d_in[8];
    const float* Wo = (const float*)d_in[9];
    const float* bo = (const float*)d_in[10];
    float* out = (float*)d_out;

    const int attn_smem = 3 * 64 * AP * (int)sizeof(float);   // 49,920 B
    cudaFuncSetAttribute(attn_kernel,
                         cudaFuncAttributeMaxDynamicSharedMemorySize, attn_smem);

    dim3 gemmGrid(D_MODEL / 128, MROWS / 128);   // (8, 32)

    sgemm_kernel<0, 1><<<gemmGrid, 256>>>(query, Wq, bq, nullptr);
    sgemm_kernel<0, 2><<<gemmGrid, 256>>>(key_,  Wk, bk, nullptr);
    sgemm_kernel<0, 3><<<gemmGrid, 256>>>(value, Wv, bv, nullptr);

    attn_kernel<<<dim3(SEQ / 64, BATCH * HEADS), 256, attn_smem>>>();

    sgemm_kernel<1, 0><<<gemmGrid, 256>>>(nullptr, Wo, bo, out);
}

// round 4
// speedup vs baseline: 1.7543x; 1.7543x over previous
#include <cuda_runtime.h>
#include <cuda_bf16.h>
#include <math.h>
#include <stdint.h>

#define HEADS   16
#define D_MODEL 1024
#define DK      64
#define BATCH   2
#define SEQ     2048
#define MROWS   (BATCH * SEQ)   // 4096

// ---------------- scratch (device globals; no allocation allowed) ----------
__device__ __align__(16) float g_q[MROWS * D_MODEL];     // [B*H, S, DK]
__device__ __align__(16) float g_k[MROWS * D_MODEL];
__device__ __align__(16) float g_v[MROWS * D_MODEL];
__device__ __align__(16) float g_ctx[MROWS * D_MODEL];   // [B, S, D_MODEL]
// split-precision operands for tensor-core GEMMs
__device__ __align__(16) __nv_bfloat16 g_ah[MROWS * D_MODEL];     // A hi [M][K]
__device__ __align__(16) __nv_bfloat16 g_al[MROWS * D_MODEL];     // A lo
__device__ __align__(16) __nv_bfloat16 g_wh[D_MODEL * D_MODEL];   // W^T hi [N][K]
__device__ __align__(16) __nv_bfloat16 g_wl[D_MODEL * D_MODEL];   // W^T lo

// ---------------------------------------------------------------------------
__device__ __forceinline__ uint32_t smem_u32(const void* p) {
    uint32_t a;
    asm("{ .reg .u64 t; cvta.to.shared.u64 t, %1; cvt.u32.u64 %0, t; }"
        : "=r"(a) : "l"(p));
    return a;
}
__device__ __forceinline__ void cpasync16(uint32_t dst, const void* src) {
    asm volatile("cp.async.cg.shared.global [%0], [%1], 16;"
                 :: "r"(dst), "l"(src) : "memory");
}
__device__ __forceinline__ uint32_t lds32(uint32_t a) {
    uint32_t v; asm volatile("ld.shared.b32 %0, [%1];" : "=r"(v) : "r"(a));
    return v;
}
__device__ __forceinline__ void mma_bf16(float* c, const uint32_t* a, const uint32_t* b) {
    asm volatile(
        "mma.sync.aligned.m16n8k16.row.col.f32.bf16.bf16.f32 "
        "{%0,%1,%2,%3}, {%4,%5,%6,%7}, {%8,%9}, {%0,%1,%2,%3};"
        : "+f"(c[0]), "+f"(c[1]), "+f"(c[2]), "+f"(c[3])
        : "r"(a[0]), "r"(a[1]), "r"(a[2]), "r"(a[3]), "r"(b[0]), "r"(b[1]));
}

// ---------------------------------------------------------------------------
// split kernels: fp32 -> bf16 hi + bf16 lo(residual)
// ---------------------------------------------------------------------------
template<int SRC_CTX>
__global__ __launch_bounds__(256) void split_kernel(const float* __restrict__ src_in)
{
    const float* src = SRC_CTX ? g_ctx : src_in;
    const int i = blockIdx.x * 256 + threadIdx.x;          // float4 index
    const float4 x = ((const float4*)src)[i];
    __nv_bfloat16 h0 = __float2bfloat16(x.x), h1 = __float2bfloat16(x.y);
    __nv_bfloat16 h2 = __float2bfloat16(x.z), h3 = __float2bfloat16(x.w);
    __nv_bfloat16 l0 = __float2bfloat16(x.x - __bfloat162float(h0));
    __nv_bfloat16 l1 = __float2bfloat16(x.y - __bfloat162float(h1));
    __nv_bfloat16 l2 = __float2bfloat16(x.z - __bfloat162float(h2));
    __nv_bfloat16 l3 = __float2bfloat16(x.w - __bfloat162float(h3));
    ((__nv_bfloat162*)g_ah)[i * 2 + 0] = __nv_bfloat162(h0, h1);
    ((__nv_bfloat162*)g_ah)[i * 2 + 1] = __nv_bfloat162(h2, h3);
    ((__nv_bfloat162*)g_al)[i * 2 + 0] = __nv_bfloat162(l0, l1);
    ((__nv_bfloat162*)g_al)[i * 2 + 1] = __nv_bfloat162(l2, l3);
}

// W [K][N] fp32 -> W^T hi/lo [N][K] bf16
__global__ __launch_bounds__(256) void splitT_kernel(const float* __restrict__ W)
{
    __shared__ float tile[32][33];
    const int bx = blockIdx.x * 32, by = blockIdx.y * 32;
    const int tx = threadIdx.x, ty = threadIdx.y;          // 32 x 8
    #pragma unroll
    for (int k = 0; k < 32; k += 8)
        tile[ty + k][tx] = W[(size_t)(by + ty + k) * D_MODEL + bx + tx];
    __syncthreads();
    #pragma unroll
    for (int k = 0; k < 32; k += 8) {
        const float v = tile[tx][ty + k];
        const __nv_bfloat16 h = __float2bfloat16(v);
        const size_t o = (size_t)(bx + ty + k) * D_MODEL + by + tx;
        g_wh[o] = h;
        g_wl[o] = __float2bfloat16(v - __bfloat162float(h));
    }
}

// ---------------------------------------------------------------------------
// mma.sync bf16x3 GEMM: C[4096x1024] = A @ W + bias
// 128x128 CTA tile, BK=32, 256 thr (8 warps, warp tile 32x64).
// smem tiles (per buffer): AH, AL [128][BK], BH, BL [128][BK], pitch 40 halves.
// DEST: 0 -> C row-major; 1/2/3 -> g_q/g_k/g_v head layout
// ---------------------------------------------------------------------------
#define PITCHB   80                       // bytes per smem row (40 halves)
#define TILE_B   (128 * PITCHB)           // 10240 B per tile
#define BUF_B    (4 * TILE_B)             // 40960 B per buffer
#define GM_SMEM  (2 * BUF_B)              // 81920 B

template<int DEST>
__global__ void __launch_bounds__(256) gemm_mma(const float* __restrict__ bias,
                                                float* __restrict__ C)
{
    extern __shared__ char smc[];
    const uint32_t sb = smem_u32(smc);
    const int tid  = threadIdx.x;
    const int lane = tid & 31, wid = tid >> 5;
    const int wm = wid & 3, wn = wid >> 2;       // warp tile (wm*32, wn*64)
    const int m0 = blockIdx.y * 128;
    const int n0 = blockIdx.x * 128;
    const int gr = lane >> 2;                    // 0..7
    const int gc = (lane & 3) << 1;              // 0,2,4,6

    float acc[2][8][4];
    #pragma unroll
    for (int mt = 0; mt < 2; mt++)
        #pragma unroll
        for (int nf = 0; nf < 8; nf++)
            #pragma unroll
            for (int j = 0; j < 4; j++) acc[mt][nf][j] = 0.0f;

    // ---- async loader for chunk ck into buffer buf ----
    auto issue = [&](int ck, int buf) {
        const int k0 = ck * 32;
        const uint32_t base = sb + buf * BUF_B;
        #pragma unroll
        for (int t = 0; t < 2; t++) {
            const int idx = tid + t * 256;       // 0..511
            const int row = idx >> 2, kc = idx & 3;
            const uint32_t d = base + row * PITCHB + kc * 16;
            const size_t ga = (size_t)(m0 + row) * D_MODEL + k0 + kc * 8;
            const size_t gb = (size_t)(n0 + row) * D_MODEL + k0 + kc * 8;
            cpasync16(d,              g_ah + ga);
            cpasync16(d + TILE_B,     g_al + ga);
            cpasync16(d + 2 * TILE_B, g_wh + gb);
            cpasync16(d + 3 * TILE_B, g_wl + gb);
        }
        asm volatile("cp.async.commit_group;" ::: "memory");
    };

    issue(0, 0);
    for (int ck = 0; ck < 32; ck++) {
        if (ck < 31) {
            issue(ck + 1, (ck + 1) & 1);
            asm volatile("cp.async.wait_group 1;" ::: "memory");
        } else {
            asm volatile("cp.async.wait_group 0;" ::: "memory");
        }
        __syncthreads();

        const uint32_t base = sb + (ck & 1) * BUF_B;
        #pragma unroll
        for (int ks = 0; ks < 2; ks++) {
            const int ko = ks * 16;
            uint32_t ah[2][4], al[2][4], bh[8][2], bl[8][2];
            #pragma unroll
            for (int mt = 0; mt < 2; mt++) {
                const uint32_t r0 = base + (wm * 32 + mt * 16 + gr) * PITCHB
                                  + (ko + gc) * 2;
                ah[mt][0] = lds32(r0);
                ah[mt][1] = lds32(r0 + 8 * PITCHB);
                ah[mt][2] = lds32(r0 + 16);
                ah[mt][3] = lds32(r0 + 8 * PITCHB + 16);
                al[mt][0] = lds32(r0 + TILE_B);
                al[mt][1] = lds32(r0 + TILE_B + 8 * PITCHB);
                al[mt][2] = lds32(r0 + TILE_B + 16);
                al[mt][3] = lds32(r0 + TILE_B + 8 * PITCHB + 16);
            }
            #pragma unroll
            for (int nf = 0; nf < 8; nf++) {
                const uint32_t r0 = base + 2 * TILE_B
                                  + (wn * 64 + nf * 8 + gr) * PITCHB + (ko + gc) * 2;
                bh[nf][0] = lds32(r0);
                bh[nf][1] = lds32(r0 + 16);
                bl[nf][0] = lds32(r0 + TILE_B);
                bl[nf][1] = lds32(r0 + TILE_B + 16);
            }
            #pragma unroll
            for (int mt = 0; mt < 2; mt++)
                #pragma unroll
                for (int nf = 0; nf < 8; nf++) {
                    mma_bf16(acc[mt][nf], ah[mt], bh[nf]);
                    mma_bf16(acc[mt][nf], ah[mt], bl[nf]);
                    mma_bf16(acc[mt][nf], al[mt], bh[nf]);
                }
        }
        __syncthreads();
    }

    // ---- epilogue: bias add + store ----
    #pragma unroll
    for (int mt = 0; mt < 2; mt++) {
        const int row0 = m0 + wm * 32 + mt * 16 + gr;
        #pragma unroll
        for (int nf = 0; nf < 8; nf++) {
            const int col = n0 + wn * 64 + nf * 8 + gc;
            const float2 b2 = *(const float2*)&bias[col];
            float2 v0, v1;
            v0.x = acc[mt][nf][0] + b2.x;  v0.y = acc[mt][nf][1] + b2.y;
            v1.x = acc[mt][nf][2] + b2.x;  v1.y = acc[mt][nf][3] + b2.y;
            if (DEST == 0) {
                *(float2*)&C[(size_t)row0 * D_MODEL + col]       = v0;
                *(float2*)&C[(size_t)(row0 + 8) * D_MODEL + col] = v1;
            } else {
                float* dst = (DEST == 1) ? g_q : (DEST == 2) ? g_k : g_v;
                const int h = col >> 6, d = col & (DK - 1);
                {
                    const int b = row0 >> 11, s2 = row0 & (SEQ - 1);
                    *(float2*)&dst[((size_t)(b * HEADS + h) * SEQ + s2) * DK + d] = v0;
                }
                {
                    const int r1 = row0 + 8;
                    const int b = r1 >> 11, s2 = r1 & (SEQ - 1);
                    *(float2*)&dst[((size_t)(b * HEADS + h) * SEQ + s2) * DK + d] = v1;
                }
            }
        }
    }
}

// ---------------------------------------------------------------------------
// Flash attention, fp32, float4-vectorized smem with XOR swizzle (R2 design).
// ---------------------------------------------------------------------------
__device__ __forceinline__ float redmax16(float v) {
    #pragma unroll
    for (int off = 8; off > 0; off >>= 1)
        v = fmaxf(v, __shfl_xor_sync(0xffffffffu, v, off, 16));
    return v;
}
__device__ __forceinline__ float redsum16(float v) {
    #pragma unroll
    for (int off = 8; off > 0; off >>= 1)
        v += __shfl_xor_sync(0xffffffffu, v, off, 16);
    return v;
}

__global__ __launch_bounds__(256) void attn_kernel()
{
    extern __shared__ float sm[];
    float4* Q4 = (float4*)sm;           // [64][16] float4
    float4* K4 = Q4 + 1024;             // reused as P
    float4* V4 = K4 + 1024;

    const int tid = threadIdx.x;
    const int ty  = tid >> 4;           // 0..15 -> query rows 4*ty..
    const int tx  = tid & 15;           // 0..15 -> key/d cols 4*tx..
    const int qt  = blockIdx.x;
    const int bh  = blockIdx.y;

    const float4* Qg = (const float4*)(g_q + (size_t)bh * SEQ * DK + (size_t)qt * 64 * DK);
    const float4* Kg = (const float4*)(g_k + (size_t)bh * SEQ * DK);
    const float4* Vg = (const float4*)(g_v + (size_t)bh * SEQ * DK);

    for (int i = tid; i < 1024; i += 256) {
        const int r = i >> 4, ch = i & 15;
        float4 q = Qg[r * 16 + ch];
        q.x *= 0.125f; q.y *= 0.125f; q.z *= 0.125f; q.w *= 0.125f;
        Q4[r * 16 + (ch ^ (r >> 2))] = q;
    }

    float4 o4[4];
    float m_i[4], l_i[4];
    #pragma unroll
    for (int r = 0; r < 4; r++) {
        m_i[r] = -INFINITY; l_i[r] = 0.0f;
        o4[r] = make_float4(0.f, 0.f, 0.f, 0.f);
    }
    __syncthreads();

    for (int kt = 0; kt < SEQ / 64; kt++) {
        const float4* Kt = Kg + kt * 1024;
        const float4* Vt = Vg + kt * 1024;
        for (int i = tid; i < 1024; i += 256) {
            const int r = i >> 4, ch = i & 15;
            K4[r * 16 + (ch ^ (r >> 2))] = Kt[r * 16 + ch];
            V4[r * 16 + (ch ^ (r >> 2))] = Vt[r * 16 + ch];
        }
        __syncthreads();

        float s[4][4];
        #pragma unroll
        for (int r = 0; r < 4; r++)
            #pragma unroll
            for (int c = 0; c < 4; c++) s[r][c] = 0.0f;

        #pragma unroll 4
        for (int d0 = 0; d0 < 16; d0++) {
            float4 qv[4], kv[4];
            const int qc = d0 ^ ty;
            const int kc = d0 ^ tx;
            #pragma unroll
            for (int r = 0; r < 4; r++) qv[r] = Q4[(ty * 4 + r) * 16 + qc];
            #pragma unroll
            for (int c = 0; c < 4; c++) kv[c] = K4[(tx * 4 + c) * 16 + kc];
            #pragma unroll
            for (int r = 0; r < 4; r++)
                #pragma unroll
                for (int c = 0; c < 4; c++) {
                    s[r][c] = fmaf(qv[r].x, kv[c].x, s[r][c]);
                    s[r][c] = fmaf(qv[r].y, kv[c].y, s[r][c]);
                    s[r][c] = fmaf(qv[r].z, kv[c].z, s[r][c]);
                    s[r][c] = fmaf(qv[r].w, kv[c].w, s[r][c]);
                }
        }

        float p[4][4];
        #pragma unroll
        for (int r = 0; r < 4; r++) {
            float tm = fmaxf(fmaxf(s[r][0], s[r][1]), fmaxf(s[r][2], s[r][3]));
            tm = redmax16(tm);
            const float mn = fmaxf(m_i[r], tm);
            const float alpha = __expf(m_i[r] - mn);
            float rs = 0.0f;
            #pragma unroll
            for (int c = 0; c < 4; c++) { p[r][c] = __expf(s[r][c] - mn); rs += p[r][c]; }
            rs = redsum16(rs);
            l_i[r] = l_i[r] * alpha + rs;
            m_i[r] = mn;
            o4[r].x *= alpha; o4[r].y *= alpha; o4[r].z *= alpha; o4[r].w *= alpha;
        }

        __syncthreads();   // done reading K4 -> overwrite with P
        #pragma unroll
        for (int r = 0; r < 4; r++)
            K4[(ty * 4 + r) * 16 + (tx ^ ty)] =
                make_float4(p[r][0], p[r][1], p[r][2], p[r][3]);
        __syncthreads();

        #pragma unroll 4
        for (int j0 = 0; j0 < 16; j0++) {
            float4 pr[4], vr[4];
            const int pc = j0 ^ ty;
            const int vc = tx ^ j0;
            #pragma unroll
            for (int r = 0; r < 4; r++) pr[r] = K4[(ty * 4 + r) * 16 + pc];
            #pragma unroll
            for (int jj = 0; jj < 4; jj++) vr[jj] = V4[(j0 * 4 + jj) * 16 + vc];
            #pragma unroll
            for (int r = 0; r < 4; r++) {
                o4[r].x = fmaf(pr[r].x, vr[0].x, o4[r].x);
                o4[r].y = fmaf(pr[r].x, vr[0].y, o4[r].y);
                o4[r].z = fmaf(pr[r].x, vr[0].z, o4[r].z);
                o4[r].w = fmaf(pr[r].x, vr[0].w, o4[r].w);
                o4[r].x = fmaf(pr[r].y, vr[1].x, o4[r].x);
                o4[r].y = fmaf(pr[r].y, vr[1].y, o4[r].y);
                o4[r].z = fmaf(pr[r].y, vr[1].z, o4[r].z);
                o4[r].w = fmaf(pr[r].y, vr[1].w, o4[r].w);
                o4[r].x = fmaf(pr[r].z, vr[2].x, o4[r].x);
                o4[r].y = fmaf(pr[r].z, vr[2].y, o4[r].y);
                o4[r].z = fmaf(pr[r].z, vr[2].z, o4[r].z);
                o4[r].w = fmaf(pr[r].z, vr[2].w, o4[r].w);
                o4[r].x = fmaf(pr[r].w, vr[3].x, o4[r].x);
                o4[r].y = fmaf(pr[r].w, vr[3].y, o4[r].y);
                o4[r].z = fmaf(pr[r].w, vr[3].z, o4[r].z);
                o4[r].w = fmaf(pr[r].w, vr[3].w, o4[r].w);
            }
        }
        __syncthreads();   // before next tile overwrites K4/V4
    }

    const int b = bh >> 4, h = bh & 15;
    #pragma unroll
    for (int r = 0; r < 4; r++) {
        const float inv = 1.0f / l_i[r];
        const int srow = qt * 64 + ty * 4 + r;
        float4 v = o4[r];
        v.x *= inv; v.y *= inv; v.z *= inv; v.w *= inv;
        ((float4*)g_ctx)[(size_t)(b * SEQ + srow) * (D_MODEL / 4) + h * 16 + tx] = v;
    }
}

// ---------------------------------------------------------------------------
extern "C" void kernel_launch(void* const* d_in, const int* in_sizes, int n_in,
                              void* d_out, int out_size)
{
    const float* query = (const float*)d_in[0];
    const float* key_  = (const float*)d_in[1];
    const float* value = (const float*)d_in[2];
    const float* Wq = (const float*)d_in[3];
    const float* bq = (const float*)d_in[4];
    const float* Wk = (const float*)d_in[5];
    const float* bk = (const float*)d_in[6];
    const float* Wv = (const float*)d_in[7];
    const float* bv = (const float*)d_in[8];
    const float* Wo = (const float*)d_in[9];
    const float* bo = (const float*)d_in[10];
    float* out = (float*)d_out;

    cudaFuncSetAttribute(gemm_mma<0>, cudaFuncAttributeMaxDynamicSharedMemorySize, GM_SMEM);
    cudaFuncSetAttribute(gemm_mma<1>, cudaFuncAttributeMaxDynamicSharedMemorySize, GM_SMEM);
    cudaFuncSetAttribute(gemm_mma<2>, cudaFuncAttributeMaxDynamicSharedMemorySize, GM_SMEM);
    cudaFuncSetAttribute(gemm_mma<3>, cudaFuncAttributeMaxDynamicSharedMemorySize, GM_SMEM);
    const int attn_smem = 3 * 64 * 64 * (int)sizeof(float);   // 49152
    cudaFuncSetAttribute(attn_kernel, cudaFuncAttributeMaxDynamicSharedMemorySize, attn_smem);

    const dim3 gemmGrid(D_MODEL / 128, MROWS / 128);   // (8, 32)
    const dim3 tGrid(32, 32), tBlk(32, 8);
    const int splitBlocks = (MROWS * D_MODEL / 4) / 256;   // 4096

    splitT_kernel<<<tGrid, tBlk>>>(Wq);
    split_kernel<0><<<splitBlocks, 256>>>(query);
    gemm_mma<1><<<gemmGrid, 256, GM_SMEM>>>(bq, nullptr);

    splitT_kernel<<<tGrid, tBlk>>>(Wk);
    split_kernel<0><<<splitBlocks, 256>>>(key_);
    gemm_mma<2><<<gemmGrid, 256, GM_SMEM>>>(bk, nullptr);

    splitT_kernel<<<tGrid, tBlk>>>(Wv);
    split_kernel<0><<<splitBlocks, 256>>>(value);
    gemm_mma<3><<<gemmGrid, 256, GM_SMEM>>>(bv, nullptr);

    attn_kernel<<<dim3(SEQ / 64, BATCH * HEADS), 256, attn_smem>>>();

    splitT_kernel<<<tGrid, tBlk>>>(Wo);
    split_kernel<1><<<splitBlocks, 256>>>(nullptr);
    gemm_mma<0><<<gemmGrid, 256, GM_SMEM>>>(bo, out);
}

// round 5
// speedup vs baseline: 3.2948x; 1.8782x over previous
#include <cuda_runtime.h>
#include <cuda_bf16.h>
#include <math.h>
#include <stdint.h>

#define HEADS   16
#define D_MODEL 1024
#define DK      64
#define BATCH   2
#define SEQ     2048
#define MROWS   (BATCH * SEQ)   // 4096

// ---------------- scratch (device globals; no allocation allowed) ----------
// split-precision activations for GEMMs (also attention output buffer)
__device__ __align__(16) __nv_bfloat16 g_ah[MROWS * D_MODEL];     // A hi [M][K]
__device__ __align__(16) __nv_bfloat16 g_al[MROWS * D_MODEL];     // A lo
__device__ __align__(16) __nv_bfloat16 g_wh[D_MODEL * D_MODEL];   // W^T hi [N][K]
__device__ __align__(16) __nv_bfloat16 g_wl[D_MODEL * D_MODEL];   // W^T lo
// attention operands, split bf16
__device__ __align__(16) __nv_bfloat16 g_qh[MROWS * D_MODEL];     // [bh][s][d] (pre-scaled 1/8)
__device__ __align__(16) __nv_bfloat16 g_ql[MROWS * D_MODEL];
__device__ __align__(16) __nv_bfloat16 g_kh[MROWS * D_MODEL];     // [bh][s][d]
__device__ __align__(16) __nv_bfloat16 g_kl[MROWS * D_MODEL];
__device__ __align__(16) __nv_bfloat16 g_vth[MROWS * D_MODEL];    // [bh][d][s] (transposed)
__device__ __align__(16) __nv_bfloat16 g_vtl[MROWS * D_MODEL];

// ---------------------------------------------------------------------------
__device__ __forceinline__ uint32_t smem_u32(const void* p) {
    uint32_t a;
    asm("{ .reg .u64 t; cvta.to.shared.u64 t, %1; cvt.u32.u64 %0, t; }"
        : "=r"(a) : "l"(p));
    return a;
}
__device__ __forceinline__ void cpasync16(uint32_t dst, const void* src) {
    asm volatile("cp.async.cg.shared.global [%0], [%1], 16;"
                 :: "r"(dst), "l"(src) : "memory");
}
__device__ __forceinline__ uint32_t lds32(uint32_t a) {
    uint32_t v; asm volatile("ld.shared.b32 %0, [%1];" : "=r"(v) : "r"(a));
    return v;
}
__device__ __forceinline__ void mma_bf16(float* c, const uint32_t* a, const uint32_t* b) {
    asm volatile(
        "mma.sync.aligned.m16n8k16.row.col.f32.bf16.bf16.f32 "
        "{%0,%1,%2,%3}, {%4,%5,%6,%7}, {%8,%9}, {%0,%1,%2,%3};"
        : "+f"(c[0]), "+f"(c[1]), "+f"(c[2]), "+f"(c[3])
        : "r"(a[0]), "r"(a[1]), "r"(a[2]), "r"(a[3]), "r"(b[0]), "r"(b[1]));
}
// pack two floats -> bf16x2 with x in the LOW half (element order = memory order)
__device__ __forceinline__ uint32_t pack_bf16(float x, float y) {
    uint32_t r;
    asm("cvt.rn.bf16x2.f32 %0, %1, %2;" : "=r"(r) : "f"(y), "f"(x));
    return r;
}
// split (x,y) into hi bf16x2 + lo(residual) bf16x2
__device__ __forceinline__ void split2(float x, float y, uint32_t& hi, uint32_t& lo) {
    hi = pack_bf16(x, y);
    const float hx = __uint_as_float(hi << 16);
    const float hy = __uint_as_float(hi & 0xffff0000u);
    lo = pack_bf16(x - hx, y - hy);
}

// ---------------------------------------------------------------------------
// split kernels: fp32 -> bf16 hi + bf16 lo(residual)
// ---------------------------------------------------------------------------
__global__ __launch_bounds__(256) void split_kernel(const float* __restrict__ src)
{
    const int i = blockIdx.x * 256 + threadIdx.x;          // float4 index
    const float4 x = ((const float4*)src)[i];
    uint32_t h0, l0, h1, l1;
    split2(x.x, x.y, h0, l0);
    split2(x.z, x.w, h1, l1);
    ((uint32_t*)g_ah)[i * 2 + 0] = h0;
    ((uint32_t*)g_ah)[i * 2 + 1] = h1;
    ((uint32_t*)g_al)[i * 2 + 0] = l0;
    ((uint32_t*)g_al)[i * 2 + 1] = l1;
}

// W [K][N] fp32 -> W^T hi/lo [N][K] bf16
__global__ __launch_bounds__(256) void splitT_kernel(const float* __restrict__ W)
{
    __shared__ float tile[32][33];
    const int bx = blockIdx.x * 32, by = blockIdx.y * 32;
    const int tx = threadIdx.x, ty = threadIdx.y;          // 32 x 8
    #pragma unroll
    for (int k = 0; k < 32; k += 8)
        tile[ty + k][tx] = W[(size_t)(by + ty + k) * D_MODEL + bx + tx];
    __syncthreads();
    #pragma unroll
    for (int k = 0; k < 32; k += 8) {
        const float v = tile[tx][ty + k];
        const __nv_bfloat16 h = __float2bfloat16(v);
        const size_t o = (size_t)(bx + ty + k) * D_MODEL + by + tx;
        g_wh[o] = h;
        g_wl[o] = __float2bfloat16(v - __bfloat162float(h));
    }
}

// ---------------------------------------------------------------------------
// mma.sync bf16x3 GEMM: C[4096x1024] = A @ W + bias
// 128x128 CTA tile, BK=32, 256 thr (8 warps, warp tile 32x64).
// DEST: 0 -> C fp32 row-major; 1 -> g_qh/g_ql (scaled 1/8); 2 -> g_kh/g_kl;
//       3 -> g_vth/g_vtl transposed [bh][d][s]
// ---------------------------------------------------------------------------
#define PITCHB   80                       // bytes per smem row (40 halves)
#define TILE_B   (128 * PITCHB)           // 10240 B per tile
#define BUF_B    (4 * TILE_B)             // 40960 B per buffer
#define GM_SMEM  (2 * BUF_B)              // 81920 B

template<int DEST>
__global__ void __launch_bounds__(256) gemm_mma(const float* __restrict__ bias,
                                                float* __restrict__ C)
{
    extern __shared__ char smc[];
    const uint32_t sb = smem_u32(smc);
    const int tid  = threadIdx.x;
    const int lane = tid & 31, wid = tid >> 5;
    const int wm = wid & 3, wn = wid >> 2;       // warp tile (wm*32, wn*64)
    const int m0 = blockIdx.y * 128;
    const int n0 = blockIdx.x * 128;
    const int gr = lane >> 2;                    // 0..7
    const int gc = (lane & 3) << 1;              // 0,2,4,6

    float acc[2][8][4];
    #pragma unroll
    for (int mt = 0; mt < 2; mt++)
        #pragma unroll
        for (int nf = 0; nf < 8; nf++)
            #pragma unroll
            for (int j = 0; j < 4; j++) acc[mt][nf][j] = 0.0f;

    auto issue = [&](int ck, int buf) {
        const int k0 = ck * 32;
        const uint32_t base = sb + buf * BUF_B;
        #pragma unroll
        for (int t = 0; t < 2; t++) {
            const int idx = tid + t * 256;       // 0..511
            const int row = idx >> 2, kc = idx & 3;
            const uint32_t d = base + row * PITCHB + kc * 16;
            const size_t ga = (size_t)(m0 + row) * D_MODEL + k0 + kc * 8;
            const size_t gb = (size_t)(n0 + row) * D_MODEL + k0 + kc * 8;
            cpasync16(d,              g_ah + ga);
            cpasync16(d + TILE_B,     g_al + ga);
            cpasync16(d + 2 * TILE_B, g_wh + gb);
            cpasync16(d + 3 * TILE_B, g_wl + gb);
        }
        asm volatile("cp.async.commit_group;" ::: "memory");
    };

    issue(0, 0);
    for (int ck = 0; ck < 32; ck++) {
        if (ck < 31) {
            issue(ck + 1, (ck + 1) & 1);
            asm volatile("cp.async.wait_group 1;" ::: "memory");
        } else {
            asm volatile("cp.async.wait_group 0;" ::: "memory");
        }
        __syncthreads();

        const uint32_t base = sb + (ck & 1) * BUF_B;
        #pragma unroll
        for (int ks = 0; ks < 2; ks++) {
            const int ko = ks * 16;
            uint32_t ah[2][4], al[2][4], bh[8][2], bl[8][2];
            #pragma unroll
            for (int mt = 0; mt < 2; mt++) {
                const uint32_t r0 = base + (wm * 32 + mt * 16 + gr) * PITCHB
                                  + (ko + gc) * 2;
                ah[mt][0] = lds32(r0);
                ah[mt][1] = lds32(r0 + 8 * PITCHB);
                ah[mt][2] = lds32(r0 + 16);
                ah[mt][3] = lds32(r0 + 8 * PITCHB + 16);
                al[mt][0] = lds32(r0 + TILE_B);
                al[mt][1] = lds32(r0 + TILE_B + 8 * PITCHB);
                al[mt][2] = lds32(r0 + TILE_B + 16);
                al[mt][3] = lds32(r0 + TILE_B + 8 * PITCHB + 16);
            }
            #pragma unroll
            for (int nf = 0; nf < 8; nf++) {
                const uint32_t r0 = base + 2 * TILE_B
                                  + (wn * 64 + nf * 8 + gr) * PITCHB + (ko + gc) * 2;
                bh[nf][0] = lds32(r0);
                bh[nf][1] = lds32(r0 + 16);
                bl[nf][0] = lds32(r0 + TILE_B);
                bl[nf][1] = lds32(r0 + TILE_B + 16);
            }
            #pragma unroll
            for (int mt = 0; mt < 2; mt++)
                #pragma unroll
                for (int nf = 0; nf < 8; nf++) {
                    mma_bf16(acc[mt][nf], ah[mt], bh[nf]);
                    mma_bf16(acc[mt][nf], ah[mt], bl[nf]);
                    mma_bf16(acc[mt][nf], al[mt], bh[nf]);
                }
        }
        __syncthreads();
    }

    // ---- epilogue ----
    #pragma unroll
    for (int mt = 0; mt < 2; mt++) {
        const int row0 = m0 + wm * 32 + mt * 16 + gr;
        #pragma unroll
        for (int nf = 0; nf < 8; nf++) {
            const int col = n0 + wn * 64 + nf * 8 + gc;
            const float2 b2 = *(const float2*)&bias[col];
            float2 v0, v1;
            v0.x = acc[mt][nf][0] + b2.x;  v0.y = acc[mt][nf][1] + b2.y;
            v1.x = acc[mt][nf][2] + b2.x;  v1.y = acc[mt][nf][3] + b2.y;
            if (DEST == 0) {
                *(float2*)&C[(size_t)row0 * D_MODEL + col]       = v0;
                *(float2*)&C[(size_t)(row0 + 8) * D_MODEL + col] = v1;
            } else if (DEST == 1 || DEST == 2) {
                if (DEST == 1) {   // fold softmax scale into Q (exact: pow2)
                    v0.x *= 0.125f; v0.y *= 0.125f; v1.x *= 0.125f; v1.y *= 0.125f;
                }
                uint32_t h0, l0, h1, l1;
                split2(v0.x, v0.y, h0, l0);
                split2(v1.x, v1.y, h1, l1);
                uint32_t* dh = (uint32_t*)((DEST == 1) ? g_qh : g_kh);
                uint32_t* dl = (uint32_t*)((DEST == 1) ? g_ql : g_kl);
                const int h = col >> 6, d = col & 63;
                {
                    const int b = row0 >> 11, s = row0 & (SEQ - 1);
                    const size_t idx = ((((size_t)(b * HEADS + h)) * SEQ + s) * DK + d) >> 1;
                    dh[idx] = h0; dl[idx] = l0;
                }
                {
                    const int r1 = row0 + 8;
                    const int b = r1 >> 11, s = r1 & (SEQ - 1);
                    const size_t idx = ((((size_t)(b * HEADS + h)) * SEQ + s) * DK + d) >> 1;
                    dh[idx] = h1; dl[idx] = l1;
                }
            } else {   // DEST == 3: V transposed [bh][d][s]
                const int h = col >> 6, d = col & 63;
                #pragma unroll
                for (int e = 0; e < 4; e++) {
                    const int rr = row0 + (e >> 1) * 8;
                    const int dd = d + (e & 1);
                    const float x = (e == 0) ? v0.x : (e == 1) ? v0.y
                                  : (e == 2) ? v1.x : v1.y;
                    const int b = rr >> 11, s = rr & (SEQ - 1);
                    const size_t idx = (((size_t)(b * HEADS + h)) * DK + dd) * SEQ + s;
                    const __nv_bfloat16 hx = __float2bfloat16(x);
                    g_vth[idx] = hx;
                    g_vtl[idx] = __float2bfloat16(x - __bfloat162float(hx));
                }
            }
        }
    }
}

// ---------------------------------------------------------------------------
// Tensor-core flash attention. CTA = 64 queries x one (b,h); 4 warps.
// S = qh*kh + qh*kl + ql*kh (fp32 accum); fp32 online softmax in frags;
// P split hi/lo in regs; O += ph*vh + ph*vl + pl*vh.
// smem rows: 64 halves (128B) at pitch 144B -> conflict-free frag LDS.
// ---------------------------------------------------------------------------
#define AT_PITCH 144
#define AT_TILE  (64 * AT_PITCH)            // 9216
#define AT_KV0   (2 * AT_TILE)              // after qh, ql
#define AT_BUF   (4 * AT_TILE)              // kh,kl,vh,vl
#define AT_SMEM  (2 * AT_TILE + 2 * AT_BUF) // 92160

__global__ void __launch_bounds__(128) attn_tc()
{
    extern __shared__ char smc[];
    const uint32_t sb = smem_u32(smc);
    const int tid = threadIdx.x;
    const int lane = tid & 31, w = tid >> 5;
    const int gr = lane >> 2, gc = (lane & 3) << 1;
    const int qt = blockIdx.x;          // 0..31
    const int bh = blockIdx.y;          // 0..31

    const __nv_bfloat16* Qh = g_qh + ((size_t)bh * SEQ + qt * 64) * DK;
    const __nv_bfloat16* Ql = g_ql + ((size_t)bh * SEQ + qt * 64) * DK;
    const __nv_bfloat16* Kh = g_kh + (size_t)bh * SEQ * DK;     // [key][d]
    const __nv_bfloat16* Kl = g_kl + (size_t)bh * SEQ * DK;
    const __nv_bfloat16* Vh = g_vth + (size_t)bh * DK * SEQ;    // [d][key]
    const __nv_bfloat16* Vl = g_vtl + (size_t)bh * DK * SEQ;

    // ---- Q tile load (once) ----
    #pragma unroll
    for (int p = 0; p < 4; p++) {
        const int idx = tid + p * 128;          // 0..511
        const int row = idx >> 3, ch = idx & 7;
        cpasync16(sb + row * AT_PITCH + ch * 16,           Qh + row * DK + ch * 8);
        cpasync16(sb + AT_TILE + row * AT_PITCH + ch * 16, Ql + row * DK + ch * 8);
    }
    asm volatile("cp.async.commit_group;" ::: "memory");

    auto issue_kv = [&](int kt, int buf) {
        const uint32_t base = sb + AT_KV0 + buf * AT_BUF;
        #pragma unroll
        for (int p = 0; p < 4; p++) {
            const int idx = tid + p * 128;
            const int row = idx >> 3, ch = idx & 7;
            const uint32_t d = base + row * AT_PITCH + ch * 16;
            const size_t ko = (size_t)(kt * 64 + row) * DK + ch * 8;
            cpasync16(d,               Kh + ko);
            cpasync16(d + AT_TILE,     Kl + ko);
            const size_t vo = (size_t)row * SEQ + kt * 64 + ch * 8;
            cpasync16(d + 2 * AT_TILE, Vh + vo);
            cpasync16(d + 3 * AT_TILE, Vl + vo);
        }
        asm volatile("cp.async.commit_group;" ::: "memory");
    };

    issue_kv(0, 0);

    float o[8][4];
    float m[2] = { -INFINITY, -INFINITY }, l[2] = { 0.0f, 0.0f };
    #pragma unroll
    for (int nf = 0; nf < 8; nf++)
        #pragma unroll
        for (int j = 0; j < 4; j++) o[nf][j] = 0.0f;

    for (int kt = 0; kt < SEQ / 64; kt++) {
        if (kt < 31) {
            issue_kv(kt + 1, (kt + 1) & 1);
            asm volatile("cp.async.wait_group 1;" ::: "memory");
        } else {
            asm volatile("cp.async.wait_group 0;" ::: "memory");
        }
        __syncthreads();

        const uint32_t base = sb + AT_KV0 + (kt & 1) * AT_BUF;

        // ---- S = Q K^T ----
        float s[8][4];
        #pragma unroll
        for (int nf = 0; nf < 8; nf++)
            #pragma unroll
            for (int j = 0; j < 4; j++) s[nf][j] = 0.0f;

        #pragma unroll
        for (int kk = 0; kk < 4; kk++) {
            uint32_t qa[4], qla[4];
            const uint32_t qrow = sb + (w * 16 + gr) * AT_PITCH + (kk * 16 + gc) * 2;
            qa[0]  = lds32(qrow);
            qa[1]  = lds32(qrow + 8 * AT_PITCH);
            qa[2]  = lds32(qrow + 16);
            qa[3]  = lds32(qrow + 8 * AT_PITCH + 16);
            qla[0] = lds32(qrow + AT_TILE);
            qla[1] = lds32(qrow + AT_TILE + 8 * AT_PITCH);
            qla[2] = lds32(qrow + AT_TILE + 16);
            qla[3] = lds32(qrow + AT_TILE + 8 * AT_PITCH + 16);
            #pragma unroll
            for (int nf = 0; nf < 8; nf++) {
                uint32_t kb[2], klb[2];
                const uint32_t krow = base + (nf * 8 + gr) * AT_PITCH + (kk * 16 + gc) * 2;
                kb[0]  = lds32(krow);
                kb[1]  = lds32(krow + 16);
                klb[0] = lds32(krow + AT_TILE);
                klb[1] = lds32(krow + AT_TILE + 16);
                mma_bf16(s[nf], qa,  kb);
                mma_bf16(s[nf], qa,  klb);
                mma_bf16(s[nf], qla, kb);
            }
        }

        // ---- online softmax (rows gr, gr+8) ----
        #pragma unroll
        for (int r = 0; r < 2; r++) {
            float tm = -INFINITY;
            #pragma unroll
            for (int nf = 0; nf < 8; nf++)
                tm = fmaxf(tm, fmaxf(s[nf][2 * r], s[nf][2 * r + 1]));
            tm = fmaxf(tm, __shfl_xor_sync(0xffffffffu, tm, 1, 4));
            tm = fmaxf(tm, __shfl_xor_sync(0xffffffffu, tm, 2, 4));
            const float mn = fmaxf(m[r], tm);
            const float alpha = __expf(m[r] - mn);
            float rs = 0.0f;
            #pragma unroll
            for (int nf = 0; nf < 8; nf++) {
                float p0 = __expf(s[nf][2 * r]     - mn);
                float p1 = __expf(s[nf][2 * r + 1] - mn);
                s[nf][2 * r] = p0; s[nf][2 * r + 1] = p1;
                rs += p0 + p1;
            }
            rs += __shfl_xor_sync(0xffffffffu, rs, 1, 4);
            rs += __shfl_xor_sync(0xffffffffu, rs, 2, 4);
            l[r] = l[r] * alpha + rs;
            m[r] = mn;
            #pragma unroll
            for (int nf = 0; nf < 8; nf++) {
                o[nf][2 * r]     *= alpha;
                o[nf][2 * r + 1] *= alpha;
            }
        }

        // ---- O += P V ----
        #pragma unroll
        for (int kk = 0; kk < 4; kk++) {
            uint32_t ph[4], pl[4];
            split2(s[2 * kk][0],     s[2 * kk][1],     ph[0], pl[0]);
            split2(s[2 * kk][2],     s[2 * kk][3],     ph[1], pl[1]);
            split2(s[2 * kk + 1][0], s[2 * kk + 1][1], ph[2], pl[2]);
            split2(s[2 * kk + 1][2], s[2 * kk + 1][3], ph[3], pl[3]);
            #pragma unroll
            for (int nf = 0; nf < 8; nf++) {
                uint32_t vb[2], vlb[2];
                const uint32_t vrow = base + 2 * AT_TILE
                                    + (nf * 8 + gr) * AT_PITCH + (kk * 16 + gc) * 2;
                vb[0]  = lds32(vrow);
                vb[1]  = lds32(vrow + 16);
                vlb[0] = lds32(vrow + AT_TILE);
                vlb[1] = lds32(vrow + AT_TILE + 16);
                mma_bf16(o[nf], ph, vb);
                mma_bf16(o[nf], ph, vlb);
                mma_bf16(o[nf], pl, vb);
            }
        }
        __syncthreads();
    }

    // ---- epilogue: normalize, split, write g_ah/g_al [B,S,D_MODEL] ----
    const int b = bh >> 4, h = bh & 15;
    uint32_t* dh = (uint32_t*)g_ah;
    uint32_t* dl = (uint32_t*)g_al;
    #pragma unroll
    for (int r = 0; r < 2; r++) {
        const float inv = 1.0f / l[r];
        const int srow = qt * 64 + w * 16 + gr + 8 * r;
        const size_t rowbase = (size_t)(b * SEQ + srow) * D_MODEL;
        #pragma unroll
        for (int nf = 0; nf < 8; nf++) {
            const float x = o[nf][2 * r] * inv;
            const float y = o[nf][2 * r + 1] * inv;
            uint32_t hi, lo;
            split2(x, y, hi, lo);
            const size_t idx = (rowbase + h * DK + nf * 8 + gc) >> 1;
            dh[idx] = hi; dl[idx] = lo;
        }
    }
}

// ---------------------------------------------------------------------------
extern "C" void kernel_launch(void* const* d_in, const int* in_sizes, int n_in,
                              void* d_out, int out_size)
{
    const float* query = (const float*)d_in[0];
    const float* key_  = (const float*)d_in[1];
    const float* value = (const float*)d_in[2];
    const float* Wq = (const float*)d_in[3];
    const float* bq = (const float*)d_in[4];
    const float* Wk = (const float*)d_in[5];
    const float* bk = (const float*)d_in[6];
    const float* Wv = (const float*)d_in[7];
    const float* bv = (const float*)d_in[8];
    const float* Wo = (const float*)d_in[9];
    const float* bo = (const float*)d_in[10];
    float* out = (float*)d_out;

    cudaFuncSetAttribute(gemm_mma<0>, cudaFuncAttributeMaxDynamicSharedMemorySize, GM_SMEM);
    cudaFuncSetAttribute(gemm_mma<1>, cudaFuncAttributeMaxDynamicSharedMemorySize, GM_SMEM);
    cudaFuncSetAttribute(gemm_mma<2>, cudaFuncAttributeMaxDynamicSharedMemorySize, GM_SMEM);
    cudaFuncSetAttribute(gemm_mma<3>, cudaFuncAttributeMaxDynamicSharedMemorySize, GM_SMEM);
    cudaFuncSetAttribute(attn_tc, cudaFuncAttributeMaxDynamicSharedMemorySize, AT_SMEM);

    const dim3 gemmGrid(D_MODEL / 128, MROWS / 128);   // (8, 32)
    const dim3 tGrid(32, 32), tBlk(32, 8);
    const int splitBlocks = (MROWS * D_MODEL / 4) / 256;   // 4096

    splitT_kernel<<<tGrid, tBlk>>>(Wq);
    split_kernel<<<splitBlocks, 256>>>(query);
    gemm_mma<1><<<gemmGrid, 256, GM_SMEM>>>(bq, nullptr);

    splitT_kernel<<<tGrid, tBlk>>>(Wk);
    split_kernel<<<splitBlocks, 256>>>(key_);
    gemm_mma<2><<<gemmGrid, 256, GM_SMEM>>>(bk, nullptr);

    splitT_kernel<<<tGrid, tBlk>>>(Wv);
    split_kernel<<<splitBlocks, 256>>>(value);
    gemm_mma<3><<<gemmGrid, 256, GM_SMEM>>>(bv, nullptr);

    attn_tc<<<dim3(SEQ / 64, BATCH * HEADS), 128, AT_SMEM>>>();

    splitT_kernel<<<tGrid, tBlk>>>(Wo);
    gemm_mma<0><<<gemmGrid, 256, GM_SMEM>>>(bo, out);
}

// round 6
// speedup vs baseline: 3.3582x; 1.0192x over previous
#include <cuda_runtime.h>
#include <cuda_bf16.h>
#include <math.h>
#include <stdint.h>

#define HEADS   16
#define D_MODEL 1024
#define DK      64
#define BATCH   2
#define SEQ     2048
#define MROWS   (BATCH * SEQ)   // 4096

// ---------------- scratch (device globals; no allocation allowed) ----------
__device__ __align__(16) __nv_bfloat16 g_ah[MROWS * D_MODEL];     // A hi [M][K]
__device__ __align__(16) __nv_bfloat16 g_al[MROWS * D_MODEL];     // A lo
__device__ __align__(16) __nv_bfloat16 g_wh[D_MODEL * D_MODEL];   // W^T hi [N][K]
__device__ __align__(16) __nv_bfloat16 g_wl[D_MODEL * D_MODEL];   // W^T lo
__device__ __align__(16) __nv_bfloat16 g_qh[MROWS * D_MODEL];     // [bh][s][d] (pre-scaled)
__device__ __align__(16) __nv_bfloat16 g_ql[MROWS * D_MODEL];
__device__ __align__(16) __nv_bfloat16 g_kh[MROWS * D_MODEL];     // [bh][s][d]
__device__ __align__(16) __nv_bfloat16 g_kl[MROWS * D_MODEL];
__device__ __align__(16) __nv_bfloat16 g_vth[MROWS * D_MODEL];    // [bh][d][s]
__device__ __align__(16) __nv_bfloat16 g_vtl[MROWS * D_MODEL];

// ---------------------------------------------------------------------------
__device__ __forceinline__ uint32_t smem_u32(const void* p) {
    uint32_t a;
    asm("{ .reg .u64 t; cvta.to.shared.u64 t, %1; cvt.u32.u64 %0, t; }"
        : "=r"(a) : "l"(p));
    return a;
}
__device__ __forceinline__ void cpasync16(uint32_t dst, const void* src) {
    asm volatile("cp.async.cg.shared.global [%0], [%1], 16;"
                 :: "r"(dst), "l"(src) : "memory");
}
__device__ __forceinline__ void ldsm4(uint32_t a, uint32_t& r0, uint32_t& r1,
                                      uint32_t& r2, uint32_t& r3) {
    asm volatile("ldmatrix.sync.aligned.m8n8.x4.shared.b16 {%0,%1,%2,%3}, [%4];"
                 : "=r"(r0), "=r"(r1), "=r"(r2), "=r"(r3) : "r"(a));
}
__device__ __forceinline__ void mma_bf16(float* c, const uint32_t* a, const uint32_t* b) {
    asm volatile(
        "mma.sync.aligned.m16n8k16.row.col.f32.bf16.bf16.f32 "
        "{%0,%1,%2,%3}, {%4,%5,%6,%7}, {%8,%9}, {%0,%1,%2,%3};"
        : "+f"(c[0]), "+f"(c[1]), "+f"(c[2]), "+f"(c[3])
        : "r"(a[0]), "r"(a[1]), "r"(a[2]), "r"(a[3]), "r"(b[0]), "r"(b[1]));
}
__device__ __forceinline__ uint32_t pack_bf16(float x, float y) {
    uint32_t r;
    asm("cvt.rn.bf16x2.f32 %0, %1, %2;" : "=r"(r) : "f"(y), "f"(x));
    return r;
}
__device__ __forceinline__ void split2(float x, float y, uint32_t& hi, uint32_t& lo) {
    hi = pack_bf16(x, y);
    const float hx = __uint_as_float(hi << 16);
    const float hy = __uint_as_float(hi & 0xffff0000u);
    lo = pack_bf16(x - hx, y - hy);
}

// ---------------------------------------------------------------------------
// split kernels: fp32 -> bf16 hi + bf16 lo(residual)
// ---------------------------------------------------------------------------
__global__ __launch_bounds__(256) void split_kernel(const float* __restrict__ src)
{
    const int i = blockIdx.x * 256 + threadIdx.x;          // float4 index
    const float4 x = ((const float4*)src)[i];
    uint32_t h0, l0, h1, l1;
    split2(x.x, x.y, h0, l0);
    split2(x.z, x.w, h1, l1);
    ((uint32_t*)g_ah)[i * 2 + 0] = h0;
    ((uint32_t*)g_ah)[i * 2 + 1] = h1;
    ((uint32_t*)g_al)[i * 2 + 0] = l0;
    ((uint32_t*)g_al)[i * 2 + 1] = l1;
}

// W [K][N] fp32 -> W^T hi/lo [N][K] bf16
__global__ __launch_bounds__(256) void splitT_kernel(const float* __restrict__ W)
{
    __shared__ float tile[32][33];
    const int bx = blockIdx.x * 32, by = blockIdx.y * 32;
    const int tx = threadIdx.x, ty = threadIdx.y;          // 32 x 8
    #pragma unroll
    for (int k = 0; k < 32; k += 8)
        tile[ty + k][tx] = W[(size_t)(by + ty + k) * D_MODEL + bx + tx];
    __syncthreads();
    #pragma unroll
    for (int k = 0; k < 32; k += 8) {
        const float v = tile[tx][ty + k];
        const __nv_bfloat16 h = __float2bfloat16(v);
        const size_t o = (size_t)(bx + ty + k) * D_MODEL + by + tx;
        g_wh[o] = h;
        g_wl[o] = __float2bfloat16(v - __bfloat162float(h));
    }
}

// ---------------------------------------------------------------------------
// mma.sync bf16x3 GEMM: C[4096x1024] = A @ W + bias (ldmatrix frag loads)
// 128x128 CTA tile, BK=32, 256 thr (8 warps, warp tile 32x64).
// DEST: 0 -> C fp32 row-major; 1 -> g_qh/g_ql (scaled 1/8); 2 -> g_kh/g_kl;
//       3 -> g_vth/g_vtl transposed [bh][d][s]
// ---------------------------------------------------------------------------
#define PITCHB   80                       // bytes per smem row (40 halves)
#define TILE_B   (128 * PITCHB)           // 10240 B per tile
#define BUF_B    (4 * TILE_B)             // 40960 B per buffer
#define GM_SMEM  (2 * BUF_B)              // 81920 B

template<int DEST>
__global__ void __launch_bounds__(256) gemm_mma(const float* __restrict__ bias,
                                                float* __restrict__ C)
{
    extern __shared__ char smc[];
    const uint32_t sb = smem_u32(smc);
    const int tid  = threadIdx.x;
    const int lane = tid & 31, wid = tid >> 5;
    const int wm = wid & 3, wn = wid >> 2;       // warp tile (wm*32, wn*64)
    const int m0 = blockIdx.y * 128;
    const int n0 = blockIdx.x * 128;
    const int gr = lane >> 2;                    // 0..7
    const int gc = (lane & 3) << 1;              // 0,2,4,6
    // ldmatrix lane -> row/koff mapping
    const int aRow  = lane & 15;                 // A: rows 0..15
    const int aKoff = (lane >> 4) << 4;          // +16B for k+8 half
    const int bRow  = ((lane >> 4) << 3) | (lane & 7);
    const int bKoff = ((lane >> 3) & 1) << 4;

    float acc[2][8][4];
    #pragma unroll
    for (int mt = 0; mt < 2; mt++)
        #pragma unroll
        for (int nf = 0; nf < 8; nf++)
            #pragma unroll
            for (int j = 0; j < 4; j++) acc[mt][nf][j] = 0.0f;

    auto issue = [&](int ck, int buf) {
        const int k0 = ck * 32;
        const uint32_t base = sb + buf * BUF_B;
        #pragma unroll
        for (int t = 0; t < 2; t++) {
            const int idx = tid + t * 256;       // 0..511
            const int row = idx >> 2, kc = idx & 3;
            const uint32_t d = base + row * PITCHB + kc * 16;
            const size_t ga = (size_t)(m0 + row) * D_MODEL + k0 + kc * 8;
            const size_t gb = (size_t)(n0 + row) * D_MODEL + k0 + kc * 8;
            cpasync16(d,              g_ah + ga);
            cpasync16(d + TILE_B,     g_al + ga);
            cpasync16(d + 2 * TILE_B, g_wh + gb);
            cpasync16(d + 3 * TILE_B, g_wl + gb);
        }
        asm volatile("cp.async.commit_group;" ::: "memory");
    };

    issue(0, 0);
    for (int ck = 0; ck < 32; ck++) {
        if (ck < 31) {
            issue(ck + 1, (ck + 1) & 1);
            asm volatile("cp.async.wait_group 1;" ::: "memory");
        } else {
            asm volatile("cp.async.wait_group 0;" ::: "memory");
        }
        __syncthreads();

        const uint32_t base = sb + (ck & 1) * BUF_B;
        #pragma unroll
        for (int ks = 0; ks < 2; ks++) {
            const int kob = ks * 32;             // byte offset of 16-wide k-step
            uint32_t ah[2][4], al[2][4], bh[8][2], bl[8][2];
            const uint32_t aaddr = base + (wm * 32 + aRow) * PITCHB + kob + aKoff;
            ldsm4(aaddr,                          ah[0][0], ah[0][1], ah[0][2], ah[0][3]);
            ldsm4(aaddr + 16 * PITCHB,            ah[1][0], ah[1][1], ah[1][2], ah[1][3]);
            ldsm4(aaddr + TILE_B,                 al[0][0], al[0][1], al[0][2], al[0][3]);
            ldsm4(aaddr + TILE_B + 16 * PITCHB,   al[1][0], al[1][1], al[1][2], al[1][3]);
            const uint32_t baddr = base + 2 * TILE_B
                                 + (wn * 64 + bRow) * PITCHB + kob + bKoff;
            #pragma unroll
            for (int j = 0; j < 4; j++) {
                ldsm4(baddr + j * 16 * PITCHB,
                      bh[2 * j][0], bh[2 * j][1], bh[2 * j + 1][0], bh[2 * j + 1][1]);
                ldsm4(baddr + j * 16 * PITCHB + TILE_B,
                      bl[2 * j][0], bl[2 * j][1], bl[2 * j + 1][0], bl[2 * j + 1][1]);
            }
            #pragma unroll
            for (int mt = 0; mt < 2; mt++)
                #pragma unroll
                for (int nf = 0; nf < 8; nf++) {
                    mma_bf16(acc[mt][nf], ah[mt], bh[nf]);
                    mma_bf16(acc[mt][nf], ah[mt], bl[nf]);
                    mma_bf16(acc[mt][nf], al[mt], bh[nf]);
                }
        }
        __syncthreads();
    }

    // ---- epilogue ----
    #pragma unroll
    for (int mt = 0; mt < 2; mt++) {
        const int row0 = m0 + wm * 32 + mt * 16 + gr;
        #pragma unroll
        for (int nf = 0; nf < 8; nf++) {
            const int col = n0 + wn * 64 + nf * 8 + gc;
            const float2 b2 = *(const float2*)&bias[col];
            float2 v0, v1;
            v0.x = acc[mt][nf][0] + b2.x;  v0.y = acc[mt][nf][1] + b2.y;
            v1.x = acc[mt][nf][2] + b2.x;  v1.y = acc[mt][nf][3] + b2.y;
            if (DEST == 0) {
                *(float2*)&C[(size_t)row0 * D_MODEL + col]       = v0;
                *(float2*)&C[(size_t)(row0 + 8) * D_MODEL + col] = v1;
            } else if (DEST == 1 || DEST == 2) {
                if (DEST == 1) {   // fold softmax scale into Q (exact: pow2)
                    v0.x *= 0.125f; v0.y *= 0.125f; v1.x *= 0.125f; v1.y *= 0.125f;
                }
                uint32_t h0, l0, h1, l1;
                split2(v0.x, v0.y, h0, l0);
                split2(v1.x, v1.y, h1, l1);
                uint32_t* dh = (uint32_t*)((DEST == 1) ? g_qh : g_kh);
                uint32_t* dl = (uint32_t*)((DEST == 1) ? g_ql : g_kl);
                const int h = col >> 6, d = col & 63;
                {
                    const int b = row0 >> 11, s = row0 & (SEQ - 1);
                    const size_t idx = ((((size_t)(b * HEADS + h)) * SEQ + s) * DK + d) >> 1;
                    dh[idx] = h0; dl[idx] = l0;
                }
                {
                    const int r1 = row0 + 8;
                    const int b = r1 >> 11, s = r1 & (SEQ - 1);
                    const size_t idx = ((((size_t)(b * HEADS + h)) * SEQ + s) * DK + d) >> 1;
                    dh[idx] = h1; dl[idx] = l1;
                }
            } else {   // DEST == 3: V transposed [bh][d][s]
                const int h = col >> 6, d = col & 63;
                #pragma unroll
                for (int e = 0; e < 4; e++) {
                    const int rr = row0 + (e >> 1) * 8;
                    const int dd = d + (e & 1);
                    const float x = (e == 0) ? v0.x : (e == 1) ? v0.y
                                  : (e == 2) ? v1.x : v1.y;
                    const int b = rr >> 11, s = rr & (SEQ - 1);
                    const size_t idx = (((size_t)(b * HEADS + h)) * DK + dd) * SEQ + s;
                    const __nv_bfloat16 hx = __float2bfloat16(x);
                    g_vth[idx] = hx;
                    g_vtl[idx] = __float2bfloat16(x - __bfloat162float(hx));
                }
            }
        }
    }
}

// ---------------------------------------------------------------------------
// Tensor-core flash attention (ldmatrix frag loads). CTA = 64 q x (b,h); 4 warps.
// ---------------------------------------------------------------------------
#define AT_PITCH 144
#define AT_TILE  (64 * AT_PITCH)            // 9216
#define AT_KV0   (2 * AT_TILE)              // after qh, ql
#define AT_BUF   (4 * AT_TILE)              // kh,kl,vh,vl
#define AT_SMEM  (2 * AT_TILE + 2 * AT_BUF) // 92160

__global__ void __launch_bounds__(128) attn_tc()
{
    extern __shared__ char smc[];
    const uint32_t sb = smem_u32(smc);
    const int tid = threadIdx.x;
    const int lane = tid & 31, w = tid >> 5;
    const int gr = lane >> 2, gc = (lane & 3) << 1;
    const int aRow  = lane & 15;
    const int aKoff = (lane >> 4) << 4;
    const int bRow  = ((lane >> 4) << 3) | (lane & 7);
    const int bKoff = ((lane >> 3) & 1) << 4;
    const int qt = blockIdx.x;          // 0..31
    const int bh = blockIdx.y;          // 0..31

    const __nv_bfloat16* Qh = g_qh + ((size_t)bh * SEQ + qt * 64) * DK;
    const __nv_bfloat16* Ql = g_ql + ((size_t)bh * SEQ + qt * 64) * DK;
    const __nv_bfloat16* Kh = g_kh + (size_t)bh * SEQ * DK;     // [key][d]
    const __nv_bfloat16* Kl = g_kl + (size_t)bh * SEQ * DK;
    const __nv_bfloat16* Vh = g_vth + (size_t)bh * DK * SEQ;    // [d][key]
    const __nv_bfloat16* Vl = g_vtl + (size_t)bh * DK * SEQ;

    // ---- Q tile load (once) ----
    #pragma unroll
    for (int p = 0; p < 4; p++) {
        const int idx = tid + p * 128;          // 0..511
        const int row = idx >> 3, ch = idx & 7;
        cpasync16(sb + row * AT_PITCH + ch * 16,           Qh + row * DK + ch * 8);
        cpasync16(sb + AT_TILE + row * AT_PITCH + ch * 16, Ql + row * DK + ch * 8);
    }
    asm volatile("cp.async.commit_group;" ::: "memory");

    auto issue_kv = [&](int kt, int buf) {
        const uint32_t base = sb + AT_KV0 + buf * AT_BUF;
        #pragma unroll
        for (int p = 0; p < 4; p++) {
            const int idx = tid + p * 128;
            const int row = idx >> 3, ch = idx & 7;
            const uint32_t d = base + row * AT_PITCH + ch * 16;
            const size_t ko = (size_t)(kt * 64 + row) * DK + ch * 8;
            cpasync16(d,               Kh + ko);
            cpasync16(d + AT_TILE,     Kl + ko);
            const size_t vo = (size_t)row * SEQ + kt * 64 + ch * 8;
            cpasync16(d + 2 * AT_TILE, Vh + vo);
            cpasync16(d + 3 * AT_TILE, Vl + vo);
        }
        asm volatile("cp.async.commit_group;" ::: "memory");
    };

    issue_kv(0, 0);

    float o[8][4];
    float m[2] = { -INFINITY, -INFINITY }, l[2] = { 0.0f, 0.0f };
    #pragma unroll
    for (int nf = 0; nf < 8; nf++)
        #pragma unroll
        for (int j = 0; j < 4; j++) o[nf][j] = 0.0f;

    for (int kt = 0; kt < SEQ / 64; kt++) {
        if (kt < 31) {
            issue_kv(kt + 1, (kt + 1) & 1);
            asm volatile("cp.async.wait_group 1;" ::: "memory");
        } else {
            asm volatile("cp.async.wait_group 0;" ::: "memory");
        }
        __syncthreads();

        const uint32_t base = sb + AT_KV0 + (kt & 1) * AT_BUF;

        // ---- S = Q K^T ----
        float s[8][4];
        #pragma unroll
        for (int nf = 0; nf < 8; nf++)
            #pragma unroll
            for (int j = 0; j < 4; j++) s[nf][j] = 0.0f;

        #pragma unroll
        for (int kk = 0; kk < 4; kk++) {
            uint32_t qa[4], qla[4];
            const uint32_t qaddr = sb + (w * 16 + aRow) * AT_PITCH + kk * 32 + aKoff;
            ldsm4(qaddr,           qa[0],  qa[1],  qa[2],  qa[3]);
            ldsm4(qaddr + AT_TILE, qla[0], qla[1], qla[2], qla[3]);
            uint32_t kb[8][2], klb[8][2];
            const uint32_t kaddr = base + bRow * AT_PITCH + kk * 32 + bKoff;
            #pragma unroll
            for (int j = 0; j < 4; j++) {
                ldsm4(kaddr + j * 16 * AT_PITCH,
                      kb[2 * j][0], kb[2 * j][1], kb[2 * j + 1][0], kb[2 * j + 1][1]);
                ldsm4(kaddr + j * 16 * AT_PITCH + AT_TILE,
                      klb[2 * j][0], klb[2 * j][1], klb[2 * j + 1][0], klb[2 * j + 1][1]);
            }
            #pragma unroll
            for (int nf = 0; nf < 8; nf++) {
                mma_bf16(s[nf], qa,  kb[nf]);
                mma_bf16(s[nf], qa,  klb[nf]);
                mma_bf16(s[nf], qla, kb[nf]);
            }
        }

        // ---- online softmax (rows gr, gr+8) ----
        #pragma unroll
        for (int r = 0; r < 2; r++) {
            float tm = -INFINITY;
            #pragma unroll
            for (int nf = 0; nf < 8; nf++)
                tm = fmaxf(tm, fmaxf(s[nf][2 * r], s[nf][2 * r + 1]));
            tm = fmaxf(tm, __shfl_xor_sync(0xffffffffu, tm, 1, 4));
            tm = fmaxf(tm, __shfl_xor_sync(0xffffffffu, tm, 2, 4));
            const float mn = fmaxf(m[r], tm);
            const float alpha = __expf(m[r] - mn);
            float rs = 0.0f;
            #pragma unroll
            for (int nf = 0; nf < 8; nf++) {
                float p0 = __expf(s[nf][2 * r]     - mn);
                float p1 = __expf(s[nf][2 * r + 1] - mn);
                s[nf][2 * r] = p0; s[nf][2 * r + 1] = p1;
                rs += p0 + p1;
            }
            rs += __shfl_xor_sync(0xffffffffu, rs, 1, 4);
            rs += __shfl_xor_sync(0xffffffffu, rs, 2, 4);
            l[r] = l[r] * alpha + rs;
            m[r] = mn;
            #pragma unroll
            for (int nf = 0; nf < 8; nf++) {
                o[nf][2 * r]     *= alpha;
                o[nf][2 * r + 1] *= alpha;
            }
        }

        // ---- O += P V ----
        #pragma unroll
        for (int kk = 0; kk < 4; kk++) {
            uint32_t ph[4], pl[4];
            split2(s[2 * kk][0],     s[2 * kk][1],     ph[0], pl[0]);
            split2(s[2 * kk][2],     s[2 * kk][3],     ph[1], pl[1]);
            split2(s[2 * kk + 1][0], s[2 * kk + 1][1], ph[2], pl[2]);
            split2(s[2 * kk + 1][2], s[2 * kk + 1][3], ph[3], pl[3]);
            uint32_t vb[8][2], vlb[8][2];
            const uint32_t vaddr = base + 2 * AT_TILE + bRow * AT_PITCH + kk * 32 + bKoff;
            #pragma unroll
            for (int j = 0; j < 4; j++) {
                ldsm4(vaddr + j * 16 * AT_PITCH,
                      vb[2 * j][0], vb[2 * j][1], vb[2 * j + 1][0], vb[2 * j + 1][1]);
                ldsm4(vaddr + j * 16 * AT_PITCH + AT_TILE,
                      vlb[2 * j][0], vlb[2 * j][1], vlb[2 * j + 1][0], vlb[2 * j + 1][1]);
            }
            #pragma unroll
            for (int nf = 0; nf < 8; nf++) {
                mma_bf16(o[nf], ph, vb[nf]);
                mma_bf16(o[nf], ph, vlb[nf]);
                mma_bf16(o[nf], pl, vb[nf]);
            }
        }
        __syncthreads();
    }

    // ---- epilogue: normalize, split, write g_ah/g_al [B,S,D_MODEL] ----
    const int b = bh >> 4, h = bh & 15;
    uint32_t* dh = (uint32_t*)g_ah;
    uint32_t* dl = (uint32_t*)g_al;
    #pragma unroll
    for (int r = 0; r < 2; r++) {
        const float inv = 1.0f / l[r];
        const int srow = qt * 64 + w * 16 + gr + 8 * r;
        const size_t rowbase = (size_t)(b * SEQ + srow) * D_MODEL;
        #pragma unroll
        for (int nf = 0; nf < 8; nf++) {
            const float x = o[nf][2 * r] * inv;
            const float y = o[nf][2 * r + 1] * inv;
            uint32_t hi, lo;
            split2(x, y, hi, lo);
            const size_t idx = (rowbase + h * DK + nf * 8 + gc) >> 1;
            dh[idx] = hi; dl[idx] = lo;
        }
    }
}

// ---------------------------------------------------------------------------
extern "C" void kernel_launch(void* const* d_in, const int* in_sizes, int n_in,
                              void* d_out, int out_size)
{
    const float* query = (const float*)d_in[0];
    const float* key_  = (const float*)d_in[1];
    const float* value = (const float*)d_in[2];
    const float* Wq = (const float*)d_in[3];
    const float* bq = (const float*)d_in[4];
    const float* Wk = (const float*)d_in[5];
    const float* bk = (const float*)d_in[6];
    const float* Wv = (const float*)d_in[7];
    const float* bv = (const float*)d_in[8];
    const float* Wo = (const float*)d_in[9];
    const float* bo = (const float*)d_in[10];
    float* out = (float*)d_out;

    cudaFuncSetAttribute(gemm_mma<0>, cudaFuncAttributeMaxDynamicSharedMemorySize, GM_SMEM);
    cudaFuncSetAttribute(gemm_mma<1>, cudaFuncAttributeMaxDynamicSharedMemorySize, GM_SMEM);
    cudaFuncSetAttribute(gemm_mma<2>, cudaFuncAttributeMaxDynamicSharedMemorySize, GM_SMEM);
    cudaFuncSetAttribute(gemm_mma<3>, cudaFuncAttributeMaxDynamicSharedMemorySize, GM_SMEM);
    cudaFuncSetAttribute(attn_tc, cudaFuncAttributeMaxDynamicSharedMemorySize, AT_SMEM);

    const dim3 gemmGrid(D_MODEL / 128, MROWS / 128);   // (8, 32)
    const dim3 tGrid(32, 32), tBlk(32, 8);
    const int splitBlocks = (MROWS * D_MODEL / 4) / 256;   // 4096

    splitT_kernel<<<tGrid, tBlk>>>(Wq);
    split_kernel<<<splitBlocks, 256>>>(query);
    gemm_mma<1><<<gemmGrid, 256, GM_SMEM>>>(bq, nullptr);

    splitT_kernel<<<tGrid, tBlk>>>(Wk);
    split_kernel<<<splitBlocks, 256>>>(key_);
    gemm_mma<2><<<gemmGrid, 256, GM_SMEM>>>(bk, nullptr);

    splitT_kernel<<<tGrid, tBlk>>>(Wv);
    split_kernel<<<splitBlocks, 256>>>(value);
    gemm_mma<3><<<gemmGrid, 256, GM_SMEM>>>(bv, nullptr);

    attn_tc<<<dim3(SEQ / 64, BATCH * HEADS), 128, AT_SMEM>>>();

    splitT_kernel<<<tGrid, tBlk>>>(Wo);
    gemm_mma<0><<<gemmGrid, 256, GM_SMEM>>>(bo, out);
}